// round 13
// baseline (speedup 1.0000x reference)
#include <cuda_runtime.h>
#include <math.h>
#include <stdint.h>

#define NB      16
#define LSEQ    2048
#define NV      10
#define NPH     19
#define NCLS    190
#define NCLSP   192
#define NBUCK   3
#define NCH128  16                                // 128-row chunks per batch
#define CH128   128
#define NSUB32  64                                // 32-position subchunks per batch
#define TAB_TOTAL (NCLS * NBUCK * NCLSP)          // 109440
#define TAB_BLOCKS ((TAB_TOTAL + 255) / 256)      // 428
#define THR_BLOCKS NB                             // 16 per-batch threshold blocks
#define HIST_BLOCKS 128                           // 256 positions per block

// ---------------- device scratch (static, allocation-free) ----------------
__device__ int g_hist32 [NB * NSUB32 * NCLSP];    // 32-gran histograms
__device__ int g_hist128[NB * NCH128 * NCLSP];    // 128-gran histograms
__device__ int g_t1[NB * NCLS];
__device__ int g_t2[NB * NCLS];
__device__ __align__(16) float2 g_tab[TAB_TOTAL]; // {e, e*vv0} per (q,bucket,cls)

// ---------------- fp32 constants (no fp64 anywhere) ----------------
__device__ __forceinline__ float omega_f() { return 6.28318530717958647692f / 19.0f; }
// cancellation-free: cos(.3w)-cos(.7w) = 2 sin(.5w) sin(.2w); ATTN_SCALE = amp/2
__device__ __forceinline__ float asf_f() {
    float om = omega_f();
    return 2.302585092994046f / (4.0f * sinf(0.5f * om) * sinf(0.2f * om));
}
__device__ __forceinline__ float cosm_f(int m) {   // cos(om*m - phi), phi = om*10.3
    return cosf(omega_f() * ((float)m - 10.3f));
}
__device__ __forceinline__ float s_of(int d, float c, float e) {
    float h0 = c - e * (float)(d * d);
    float h1 = -(float)d;
    float r  = rsqrtf((h0 * h0 + h1 * h1) * 0.5f + 1e-6f);
    float hn0 = h0 * r;
    return hn0 * rsqrtf(hn0 * hn0 * 0.5f + 1e-6f);
}
__device__ __forceinline__ float vv0_of(int d, float c, float e, float v) {
    float h0 = c - e * (float)(d * d);
    float h1 = -(float)d;
    float r  = rsqrtf((h0 * h0 + h1 * h1) * 0.5f + 1e-6f);
    return h1 * r * v;
}

// ---------------- K1: three independent segments in one launch ----------------
//   blocks [0,16):        per-batch bucket thresholds (tokens -> fo -> t1/t2)
//   blocks [16,144):      32/128-gran histograms
//   blocks [144,144+428): exp table
__global__ __launch_bounds__(256) void k1(const int* __restrict__ tokens,
                                          const float* __restrict__ C,
                                          const float* __restrict__ eps,
                                          const float* __restrict__ v) {
    int tid = threadIdx.x;
    if (blockIdx.x < THR_BLOCKS) {
        int b = blockIdx.x;
        __shared__ int   foS[NCLSP];
        __shared__ float sdf[NV], cmf[NPH];
        __shared__ int   t1S[NCLS], t2S[NCLS];
        float c = C[0], e = eps[0];
        if (tid < NCLSP) foS[tid] = 1 << 20;
        if (tid < NV)    sdf[tid] = s_of(tid, c, e);
        if (tid < NPH)   cmf[tid] = cosm_f(tid);
        if (tid < NCLS)  { t1S[tid] = 1 << 28; t2S[tid] = 1 << 28; }
        __syncthreads();
        const int4* tp4 = (const int4*)(tokens + b * LSEQ);
        #pragma unroll
        for (int i = 0; i < 2; i++) {
            int4 tv = tp4[tid * 2 + i];
            int s0 = tid * 8 + i * 4;
            atomicMin(&foS[tv.x + 10 * ((s0    ) % NPH)], s0);
            atomicMin(&foS[tv.y + 10 * ((s0 + 1) % NPH)], s0 + 1);
            atomicMin(&foS[tv.z + 10 * ((s0 + 2) % NPH)], s0 + 2);
            atomicMin(&foS[tv.w + 10 * ((s0 + 3) % NPH)], s0 + 3);
        }
        __syncthreads();
        float A = asf_f();
        for (int task = tid; task < NCLS * NPH; task += 256) {
            int q = task / NPH, p = task % NPH;
            int m = q % NPH - p; if (m < 0) m += NPH;
            float base = A * sdf[q / NPH] * cmf[m];
            int l1 = 1 << 28, l2 = 1 << 28;
            #pragma unroll
            for (int d = 0; d < NV; d++) {
                float L = base * sdf[d];
                int f = foS[d + 10 * p];
                if (L >= -6.0f)  l1 = min(l1, f);
                if (L >=  94.0f) l2 = min(l2, f);
            }
            atomicMin(&t1S[q], l1);
            atomicMin(&t2S[q], l2);
        }
        __syncthreads();
        if (tid < NCLS) {
            g_t1[b * NCLS + tid] = t1S[tid];
            g_t2[b * NCLS + tid] = t2S[tid];
        }
    } else if (blockIdx.x < THR_BLOCKS + HIST_BLOCKS) {
        __shared__ int hist[8][NCLSP];
        int bx   = blockIdx.x - THR_BLOCKS;
        int b    = bx >> 3;                  // 16 batches * 8 blocks
        int part = bx & 7;                   // 256-position segment
        if (tid < NCLSP) {
            #pragma unroll
            for (int h = 0; h < 8; h++) hist[h][tid] = 0;
        }
        __syncthreads();
        int s   = part * 256 + tid;          // 8 x 32-pos subchunks
        int cls = tokens[b * LSEQ + s] + 10 * (s % NPH);
        atomicAdd(&hist[tid >> 5][cls], 1);
        __syncthreads();
        if (tid < NCLSP) {
            int o32 = (b * NSUB32 + part * 8) * NCLSP + tid;
            int sum = 0;
            #pragma unroll
            for (int h = 0; h < 8; h++) {
                g_hist32[o32 + h * NCLSP] = hist[h][tid];
                sum += hist[h][tid];
            }
            int o128 = (b * NCH128 + part * 2) * NCLSP + tid;
            int lo = hist[0][tid] + hist[1][tid] + hist[2][tid] + hist[3][tid];
            g_hist128[o128]         = lo;
            g_hist128[o128 + NCLSP] = sum - lo;
        }
    } else {
        int idx = (blockIdx.x - THR_BLOCKS - HIST_BLOCKS) * 256 + tid;
        if (idx < TAB_TOTAL) {
            int cls    = idx % NCLSP;
            int rest   = idx / NCLSP;
            int bucket = rest % NBUCK;
            int q      = rest / NBUCK;
            float2 r = make_float2(0.f, 0.f);
            if (cls < NCLS) {
                int dt = q / NPH, tp = q % NPH;
                int d  = cls % 10, p = cls / 10;
                int m  = tp - p; if (m < 0) m += NPH;
                float c = C[0], e = eps[0], vd = v[0];
                float L   = asf_f() * s_of(dt, c, e) * s_of(d, c, e) * cosm_f(m);
                float off = -56.0f + 100.0f * (float)bucket;
                float x   = expf(fminf(L - off, 60.0f)); // clamp hits only count-0 entries
                r = make_float2(x, x * vv0_of(d, c, e, vd));
            }
            g_tab[idx] = r;
        }
    }
}

// ---------------- K2: cumulative-histogram softmax + fused epilogue ----------
// 256 blocks of 128 rows; 32 warps x 4 rows; 2 blocks/SM -> 8192 warps (~86% occ)
__global__ void __launch_bounds__(1024, 2) k_main(
    const int*   __restrict__ tokens,
    const float* __restrict__ C,        const float* __restrict__ eps,
    const float* __restrict__ o_scale,  const float* __restrict__ g_base,
    const float* __restrict__ g_slope,  const float* __restrict__ carry_amp,
    float* __restrict__ out)
{
    extern __shared__ uint16_t cnt_sh[];   // [CH128][NCLSP] inclusive cumulative counts
    __shared__ int tok_sh[CH128];
    __shared__ int cls_sh[CH128];
    __shared__ int t1S[NCLS], t2S[NCLS];

    int b   = blockIdx.x >> 4;
    int ch  = blockIdx.x & 15;              // 128-row chunk index
    int tid = threadIdx.x;
    int T0  = ch * CH128;

    // ---- phase 1 (no sync needed before it): parallel loads + per-thread bases
    int basec = 0, grp = tid / NCLSP, cl = tid % NCLSP;   // scan threads: tid < 768
    if (tid < 768) {
        // prefix over earlier 128-chunks (L2-hot, independent loads)
        for (int cc = 0; cc < ch; cc++)
            basec += g_hist128[(b * NCH128 + cc) * NCLSP + cl];
        // plus earlier 32-subchunks within this chunk
        int s32 = b * NSUB32 + ch * 4;
        #pragma unroll
        for (int j = 0; j < 3; j++)
            if (j < grp) basec += g_hist32[(s32 + j) * NCLSP + cl];
    } else if (tid < 896) {
        int i  = tid - 768;                 // 128 threads: tokens + classes
        int tk = tokens[b * LSEQ + T0 + i];
        tok_sh[i] = tk;
        cls_sh[i] = tk + 10 * ((T0 + i) % NPH);
    } else {
        int i = tid - 896;                  // 128 threads: thresholds (380 values)
        for (int q = i; q < NCLS; q += 128) {
            t1S[q] = g_t1[b * NCLS + q];
            t2S[q] = g_t2[b * NCLS + q];
        }
    }
    __syncthreads();

    // ---- phase 2: inclusive cumulative counts, four 32-row quarters in parallel
    if (tid < 768) {
        int p0 = grp * 32, cnt = basec;
        #pragma unroll 8
        for (int p = p0; p < p0 + 32; p++) {
            cnt += (cls_sh[p] == cl);
            cnt_sh[p * NCLSP + cl] = (uint16_t)cnt;
        }
    }
    __syncthreads();

    float c   = C[0],      ee = eps[0],     osc = o_scale[0];
    float ga  = g_base[0], gc = g_slope[0], ca  = carry_amp[0];

    int w = tid >> 5, lane = tid & 31;      // 32 warps, 4 rows each
    const uint32_t* cnt32 = (const uint32_t*)cnt_sh;

    #pragma unroll
    for (int rr = 0; rr < 4; rr++) {
        int r  = w * 4 + rr;
        int t  = T0 + r;
        int dt = tok_sh[r];
        int q  = dt * NPH + (t % NPH);
        int bucket = (t >= t1S[q]) + (t >= t2S[q]);

        const float4* Tb = (const float4*)(g_tab + (q * NBUCK + bucket) * NCLSP) + lane * 3;
        float4 e0 = __ldg(Tb + 0);
        float4 e1 = __ldg(Tb + 1);
        float4 e2 = __ldg(Tb + 2);

        int base = r * (NCLSP / 2) + lane * 3;   // conflict-free: 3 coprime 32
        uint32_t u0 = cnt32[base], u1 = cnt32[base + 1], u2 = cnt32[base + 2];
        float c0 = (float)(u0 & 0xffff), c1 = (float)(u0 >> 16);
        float c2 = (float)(u1 & 0xffff), c3 = (float)(u1 >> 16);
        float c4 = (float)(u2 & 0xffff), c5 = (float)(u2 >> 16);

        float den = c0 * e0.x + c1 * e0.z + c2 * e1.x + c3 * e1.z + c4 * e2.x + c5 * e2.z;
        float num = c0 * e0.y + c1 * e0.w + c2 * e1.y + c3 * e1.w + c4 * e2.y + c5 * e2.w;

        #pragma unroll
        for (int o = 16; o; o >>= 1) {
            den += __shfl_xor_sync(0xffffffffu, den, o);
            num += __shfl_xor_sync(0xffffffffu, num, o);
        }
        float attn = __fdividef(num, den);

        // fused epilogue (mirrors reference fp32 math)
        float h0 = c - ee * (float)(dt * dt);
        float h1 = -(float)dt + osc * attn;
        float rn = rsqrtf((h0 * h0 + h1 * h1) * 0.5f + 1e-6f);
        float hn0 = h0 * rn, hn1 = h1 * rn;
        float g0  = hn0 * ga + hn1 * gc;
        float g1  = hn0 * (ga - gc / c) + hn1 * gc;
        float carry = ca * (fmaxf(g1, 0.f) * hn0 - fmaxf(g0, 0.f) * hn0);
        float h1c = h1 + carry;
        float r2  = rsqrtf((h0 * h0 + h1c * h1c) * 0.5f + 1e-6f);
        const float inv_cn = 0.7071067811865475f;      // 1/sqrt(MODEL_DIM)
        float a0o = h0  * r2 * (0.1f * c * inv_cn);
        float a1o = h1c * r2 * (-c * 0.02f * inv_cn);  // -c/(50*sqrt2)
        if (lane < NV) {
            float t0  = c - ee * (float)(lane * lane);
            float t1v = -(float)lane;
            out[(b * LSEQ + t) * NV + lane] = a0o * t0 + a1o * t1v;
        }
    }
}

// ---------------- launch ----------------
extern "C" void kernel_launch(void* const* d_in, const int* in_sizes, int n_in,
                              void* d_out, int out_size) {
    const int*   tokens    = (const int*)  d_in[0];
    const float* C         = (const float*)d_in[1];
    const float* eps       = (const float*)d_in[2];
    const float* v         = (const float*)d_in[3];
    const float* o_scale   = (const float*)d_in[4];
    const float* g_base    = (const float*)d_in[5];
    const float* g_slope   = (const float*)d_in[6];
    const float* carry_amp = (const float*)d_in[7];
    float* out = (float*)d_out;

    const int smem = CH128 * NCLSP * (int)sizeof(uint16_t);   // 49152
    cudaFuncSetAttribute(k_main, cudaFuncAttributeMaxDynamicSharedMemorySize, smem);

    k1<<<THR_BLOCKS + HIST_BLOCKS + TAB_BLOCKS, 256>>>(tokens, C, eps, v);
    k_main<<<NB * NCH128, 1024, smem>>>(tokens, C, eps, o_scale, g_base, g_slope,
                                        carry_amp, out);
}

// round 14
// speedup vs baseline: 1.1312x; 1.1312x over previous
#include <cuda_runtime.h>
#include <math.h>
#include <stdint.h>

#define NB      16
#define LSEQ    2048
#define NV      10
#define NPH     19
#define NCLS    190
#define NCLSP   192
#define NBUCK   3
#define NCH128  16                                // 128-row chunks per batch
#define CH128   128
#define NSUB32  64                                // 32-position subchunks per batch
#define TAB_TOTAL (NCLS * NBUCK * NCLSP)          // 109440
#define GRID    (NB * NCH128)                     // 256 blocks

// ---------------- device scratch (static, allocation-free) ----------------
__device__ int g_hist32 [NB * NSUB32 * NCLSP];    // 32-gran histograms
__device__ int g_hist128[NB * NCH128 * NCLSP];    // 128-gran histograms
__device__ int g_t1[NB * NCLS];
__device__ int g_t2[NB * NCLS];
__device__ __align__(16) float2 g_tab[TAB_TOTAL]; // {e, e*vv0} per (q,bucket,cls)
__device__ unsigned g_bar = 0;                    // monotonic grid-barrier ticket

// ---------------- fp32 constants (no fp64 anywhere) ----------------
__device__ __forceinline__ float omega_f() { return 6.28318530717958647692f / 19.0f; }
// cancellation-free: cos(.3w)-cos(.7w) = 2 sin(.5w) sin(.2w); ATTN_SCALE = amp/2
__device__ __forceinline__ float asf_f() {
    float om = omega_f();
    return 2.302585092994046f / (4.0f * sinf(0.5f * om) * sinf(0.2f * om));
}
__device__ __forceinline__ float cosm_f(int m) {   // cos(om*m - phi), phi = om*10.3
    return cosf(omega_f() * ((float)m - 10.3f));
}
__device__ __forceinline__ float s_of(int d, float c, float e) {
    float h0 = c - e * (float)(d * d);
    float h1 = -(float)d;
    float r  = rsqrtf((h0 * h0 + h1 * h1) * 0.5f + 1e-6f);
    float hn0 = h0 * r;
    return hn0 * rsqrtf(hn0 * hn0 * 0.5f + 1e-6f);
}
__device__ __forceinline__ float vv0_of(int d, float c, float e, float v) {
    float h0 = c - e * (float)(d * d);
    float h1 = -(float)d;
    float r  = rsqrtf((h0 * h0 + h1 * h1) * 0.5f + 1e-6f);
    return h1 * r * v;
}

// ---------------- fused kernel: prep (phase A) + grid barrier + softmax (B) ----
__global__ void __launch_bounds__(1024, 2) k_fused(
    const int*   __restrict__ tokens,
    const float* __restrict__ C,        const float* __restrict__ eps,
    const float* __restrict__ v,
    const float* __restrict__ o_scale,  const float* __restrict__ g_base,
    const float* __restrict__ g_slope,  const float* __restrict__ carry_amp,
    float* __restrict__ out)
{
    extern __shared__ uint16_t cnt_sh[];   // phase B: [CH128][NCLSP] cumulative counts
    int* scratch = (int*)cnt_sh;           // phase A scratch (12288 ints)
    __shared__ int   tok_sh[CH128];
    __shared__ int   cls_sh[CH128];
    __shared__ int   t1S[NCLS], t2S[NCLS];
    __shared__ float sdf[NV], cmf[NPH];

    int bid = blockIdx.x, tid = threadIdx.x;
    int b   = bid >> 4;
    int ch  = bid & 15;
    int T0  = ch * CH128;

    float c  = C[0], ee = eps[0];

    // tokens/classes for phase B (independent of prep, overlaps phase A)
    if (tid < CH128) {
        int tk = tokens[b * LSEQ + T0 + tid];
        tok_sh[tid] = tk;
        cls_sh[tid] = tk + 10 * ((T0 + tid) % NPH);
    }

    // ================= phase A: distributed prep =================
    if (bid < NB) {
        // ---- bucket thresholds for batch `bid` ----
        int* foS = scratch;
        int* tt1 = scratch + 256;
        int* tt2 = scratch + 512;
        if (tid < NCLSP) foS[tid] = 1 << 20;
        if (tid < NV)    sdf[tid] = s_of(tid, c, ee);
        if (tid < NPH)   cmf[tid] = cosm_f(tid);
        if (tid < NCLS)  { tt1[tid] = 1 << 28; tt2[tid] = 1 << 28; }
        __syncthreads();
        int2 tv = ((const int2*)(tokens + bid * LSEQ))[tid];
        int s0 = tid * 2;
        atomicMin(&foS[tv.x + 10 * ( s0      % NPH)], s0);
        atomicMin(&foS[tv.y + 10 * ((s0 + 1) % NPH)], s0 + 1);
        __syncthreads();
        float A = asf_f();
        for (int task = tid; task < NCLS * NPH; task += 1024) {
            int q = task / NPH, p = task % NPH;
            int m = q % NPH - p; if (m < 0) m += NPH;
            float base = A * sdf[q / NPH] * cmf[m];
            int l1 = 1 << 28, l2 = 1 << 28;
            #pragma unroll
            for (int d = 0; d < NV; d++) {
                float L = base * sdf[d];
                int f = foS[d + 10 * p];
                if (L >= -6.0f)  l1 = min(l1, f);
                if (L >=  94.0f) l2 = min(l2, f);
            }
            atomicMin(&tt1[q], l1);
            atomicMin(&tt2[q], l2);
        }
        __syncthreads();
        if (tid < NCLS) {
            g_t1[bid * NCLS + tid] = tt1[tid];
            g_t2[bid * NCLS + tid] = tt2[tid];
        }
    } else if (bid < NB + 32) {
        // ---- histograms: 1024 positions (32 subchunks of 32) ----
        int bx = bid - NB, hb = bx >> 1, half = bx & 1;
        int* hist = scratch;                 // [32][NCLSP]
        for (int i = tid; i < 32 * NCLSP; i += 1024) hist[i] = 0;
        __syncthreads();
        int s   = half * 1024 + tid;
        int cls = tokens[hb * LSEQ + s] + 10 * (s % NPH);
        atomicAdd(&hist[(tid >> 5) * NCLSP + cls], 1);
        __syncthreads();
        for (int i = tid; i < 32 * NCLSP; i += 1024) {
            int sub = i / NCLSP, cl = i % NCLSP;
            g_hist32[(hb * NSUB32 + half * 32 + sub) * NCLSP + cl] = hist[i];
        }
        for (int i = tid; i < 8 * NCLSP; i += 1024) {
            int chk = i / NCLSP, cl = i % NCLSP;
            int s4  = chk * 4;
            int sm  = hist[ s4      * NCLSP + cl] + hist[(s4 + 1) * NCLSP + cl]
                    + hist[(s4 + 2) * NCLSP + cl] + hist[(s4 + 3) * NCLSP + cl];
            g_hist128[(hb * NCH128 + half * 8 + chk) * NCLSP + cl] = sm;
        }
    } else if (bid < NB + 32 + 107) {
        // ---- exp table: 1024 entries per block ----
        int idx = (bid - NB - 32) * 1024 + tid;
        if (idx < TAB_TOTAL) {
            int cls    = idx % NCLSP;
            int rest   = idx / NCLSP;
            int bucket = rest % NBUCK;
            int q      = rest / NBUCK;
            float2 r = make_float2(0.f, 0.f);
            if (cls < NCLS) {
                int dt = q / NPH, tp = q % NPH;
                int d  = cls % 10, p = cls / 10;
                int m  = tp - p; if (m < 0) m += NPH;
                float vd  = v[0];
                float L   = asf_f() * s_of(dt, c, ee) * s_of(d, c, ee) * cosm_f(m);
                float off = -56.0f + 100.0f * (float)bucket;
                float x   = expf(fminf(L - off, 60.0f)); // clamp hits only count-0 entries
                r = make_float2(x, x * vv0_of(d, c, ee, vd));
            }
            g_tab[idx] = r;
        }
    }

    // ================= grid barrier (ticket-window, no reset) =================
    // All 256 blocks are co-resident (2 blocks/SM x 148 SMs = 296 slots), so
    // spinning is deadlock-free. Launches serialize, so each launch's tickets
    // form a 256-aligned window: target = window_base + 256.
    __syncthreads();
    __threadfence();
    if (tid == 0) {
        unsigned t = atomicAdd(&g_bar, 1u);
        unsigned target = (t & ~255u) + 256u;
        while (*(volatile unsigned*)&g_bar < target) __nanosleep(64);
        __threadfence();
    }
    __syncthreads();

    // ================= phase B: cumulative-histogram softmax =================
    // parallel loads + per-thread prefix bases
    int basec = 0, grp = tid / NCLSP, cl = tid % NCLSP;   // scan threads: tid < 768
    if (tid < 768) {
        for (int cc = 0; cc < ch; cc++)
            basec += g_hist128[(b * NCH128 + cc) * NCLSP + cl];
        int s32 = b * NSUB32 + ch * 4;
        #pragma unroll
        for (int j = 0; j < 3; j++)
            if (j < grp) basec += g_hist32[(s32 + j) * NCLSP + cl];
    } else if (tid < 896) {
        int i = tid - 768;                  // 128 threads: thresholds (380 values)
        for (int q = i; q < NCLS; q += 128) {
            t1S[q] = g_t1[b * NCLS + q];
            t2S[q] = g_t2[b * NCLS + q];
        }
    }
    __syncthreads();

    // inclusive cumulative counts, four 32-row quarters in parallel
    if (tid < 768) {
        int p0 = grp * 32, cnt = basec;
        #pragma unroll 8
        for (int p = p0; p < p0 + 32; p++) {
            cnt += (cls_sh[p] == cl);
            cnt_sh[p * NCLSP + cl] = (uint16_t)cnt;
        }
    }
    __syncthreads();

    float osc = o_scale[0];
    float ga  = g_base[0], gc = g_slope[0], ca = carry_amp[0];

    int w = tid >> 5, lane = tid & 31;      // 32 warps, 4 rows each
    const uint32_t* cnt32 = (const uint32_t*)cnt_sh;

    #pragma unroll
    for (int rr = 0; rr < 4; rr++) {
        int r  = w * 4 + rr;
        int t  = T0 + r;
        int dt = tok_sh[r];
        int q  = dt * NPH + (t % NPH);
        int bucket = (t >= t1S[q]) + (t >= t2S[q]);

        const float4* Tb = (const float4*)(g_tab + (q * NBUCK + bucket) * NCLSP) + lane * 3;
        float4 e0 = __ldg(Tb + 0);
        float4 e1 = __ldg(Tb + 1);
        float4 e2 = __ldg(Tb + 2);

        int base = r * (NCLSP / 2) + lane * 3;   // conflict-free: 3 coprime 32
        uint32_t u0 = cnt32[base], u1 = cnt32[base + 1], u2 = cnt32[base + 2];
        float c0 = (float)(u0 & 0xffff), c1 = (float)(u0 >> 16);
        float c2 = (float)(u1 & 0xffff), c3 = (float)(u1 >> 16);
        float c4 = (float)(u2 & 0xffff), c5 = (float)(u2 >> 16);

        float den = c0 * e0.x + c1 * e0.z + c2 * e1.x + c3 * e1.z + c4 * e2.x + c5 * e2.z;
        float num = c0 * e0.y + c1 * e0.w + c2 * e1.y + c3 * e1.w + c4 * e2.y + c5 * e2.w;

        #pragma unroll
        for (int o = 16; o; o >>= 1) {
            den += __shfl_xor_sync(0xffffffffu, den, o);
            num += __shfl_xor_sync(0xffffffffu, num, o);
        }
        float attn = __fdividef(num, den);

        // fused epilogue (mirrors reference fp32 math)
        float h0 = c - ee * (float)(dt * dt);
        float h1 = -(float)dt + osc * attn;
        float rn = rsqrtf((h0 * h0 + h1 * h1) * 0.5f + 1e-6f);
        float hn0 = h0 * rn, hn1 = h1 * rn;
        float g0  = hn0 * ga + hn1 * gc;
        float g1  = hn0 * (ga - gc / c) + hn1 * gc;
        float carry = ca * (fmaxf(g1, 0.f) * hn0 - fmaxf(g0, 0.f) * hn0);
        float h1c = h1 + carry;
        float r2  = rsqrtf((h0 * h0 + h1c * h1c) * 0.5f + 1e-6f);
        const float inv_cn = 0.7071067811865475f;      // 1/sqrt(MODEL_DIM)
        float a0o = h0  * r2 * (0.1f * c * inv_cn);
        float a1o = h1c * r2 * (-c * 0.02f * inv_cn);  // -c/(50*sqrt2)
        if (lane < NV) {
            float t0  = c - ee * (float)(lane * lane);
            float t1v = -(float)lane;
            out[(b * LSEQ + t) * NV + lane] = a0o * t0 + a1o * t1v;
        }
    }
}

// ---------------- launch ----------------
extern "C" void kernel_launch(void* const* d_in, const int* in_sizes, int n_in,
                              void* d_out, int out_size) {
    const int*   tokens    = (const int*)  d_in[0];
    const float* C         = (const float*)d_in[1];
    const float* eps       = (const float*)d_in[2];
    const float* v         = (const float*)d_in[3];
    const float* o_scale   = (const float*)d_in[4];
    const float* g_base    = (const float*)d_in[5];
    const float* g_slope   = (const float*)d_in[6];
    const float* carry_amp = (const float*)d_in[7];
    float* out = (float*)d_out;

    const int smem = CH128 * NCLSP * (int)sizeof(uint16_t);   // 49152
    cudaFuncSetAttribute(k_fused, cudaFuncAttributeMaxDynamicSharedMemorySize, smem);

    k_fused<<<GRID, 1024, smem>>>(tokens, C, eps, v, o_scale, g_base, g_slope,
                                  carry_amp, out);
}

// round 15
// speedup vs baseline: 1.2933x; 1.1433x over previous
#include <cuda_runtime.h>
#include <math.h>
#include <stdint.h>

#define NB      16
#define LSEQ    2048
#define NV      10
#define NPH     19
#define NCLS    190
#define NCLSP   192
#define NBUCK   3
#define NCH128  16                                // 128-row chunks per batch
#define CH128   128
#define TAB_TOTAL (NCLS * NBUCK * NCLSP)          // 109440
#define GRID    (NB * NCH128)                     // 256 blocks

// ---------------- device scratch (static, allocation-free) ----------------
__device__ int g_P [NB * 64 * NCLSP];             // exclusive 32-gran prefix (within half)
__device__ int g_T0[NB * NCLSP];                  // per-class total of half 0
__device__ int g_t1[NB * NCLS];
__device__ int g_t2[NB * NCLS];
__device__ __align__(16) float2 g_tab[TAB_TOTAL]; // {e, e*vv0} per (q,bucket,cls)
__device__ unsigned g_bar = 0;                    // monotonic grid-barrier ticket

// ---------------- fp32 constants (no fp64 anywhere) ----------------
__device__ __forceinline__ float omega_f() { return 6.28318530717958647692f / 19.0f; }
// cancellation-free: cos(.3w)-cos(.7w) = 2 sin(.5w) sin(.2w); ATTN_SCALE = amp/2
__device__ __forceinline__ float asf_f() {
    float om = omega_f();
    return 2.302585092994046f / (4.0f * sinf(0.5f * om) * sinf(0.2f * om));
}
__device__ __forceinline__ float cosm_f(int m) {   // cos(om*m - phi), phi = om*10.3
    return cosf(omega_f() * ((float)m - 10.3f));
}
__device__ __forceinline__ float s_of(int d, float c, float e) {
    float h0 = c - e * (float)(d * d);
    float h1 = -(float)d;
    float r  = rsqrtf((h0 * h0 + h1 * h1) * 0.5f + 1e-6f);
    float hn0 = h0 * r;
    return hn0 * rsqrtf(hn0 * hn0 * 0.5f + 1e-6f);
}
__device__ __forceinline__ float vv0_of(int d, float c, float e, float v) {
    float h0 = c - e * (float)(d * d);
    float h1 = -(float)d;
    float r  = rsqrtf((h0 * h0 + h1 * h1) * 0.5f + 1e-6f);
    return h1 * r * v;
}

// ---------------- fused kernel: prep (phase A) + grid barrier + softmax (B) ----
__global__ void __launch_bounds__(1024, 2) k_fused(
    const int*   __restrict__ tokens,
    const float* __restrict__ C,        const float* __restrict__ eps,
    const float* __restrict__ v,
    const float* __restrict__ o_scale,  const float* __restrict__ g_base,
    const float* __restrict__ g_slope,  const float* __restrict__ carry_amp,
    float* __restrict__ out)
{
    extern __shared__ uint16_t cnt_sh[];   // phase B: [CH128][NCLSP] cumulative counts
    int* scratch = (int*)cnt_sh;           // phase A scratch (12288 ints)
    __shared__ int   tok_sh[CH128];
    __shared__ int   cls_sh[CH128];
    __shared__ int   t1S[NCLS], t2S[NCLS];
    __shared__ float sdf[NV], cmf[NPH];

    int bid = blockIdx.x, tid = threadIdx.x;
    int b   = bid >> 4;
    int ch  = bid & 15;
    int T0  = ch * CH128;

    float c  = C[0], ee = eps[0];

    // tokens/classes for phase B (independent of prep, overlaps phase A)
    if (tid < CH128) {
        int tk = tokens[b * LSEQ + T0 + tid];
        tok_sh[tid] = tk;
        cls_sh[tid] = tk + 10 * ((T0 + tid) % NPH);
    }

    // ================= phase A: distributed prep =================
    if (bid < NB) {
        // ---- bucket thresholds for batch `bid` ----
        int* foS = scratch;
        int* tt1 = scratch + 256;
        int* tt2 = scratch + 512;
        if (tid < NCLSP) foS[tid] = 1 << 20;
        if (tid < NV)    sdf[tid] = s_of(tid, c, ee);
        if (tid < NPH)   cmf[tid] = cosm_f(tid);
        if (tid < NCLS)  { tt1[tid] = 1 << 28; tt2[tid] = 1 << 28; }
        __syncthreads();
        int2 tv = ((const int2*)(tokens + bid * LSEQ))[tid];
        int s0 = tid * 2;
        atomicMin(&foS[tv.x + 10 * ( s0      % NPH)], s0);
        atomicMin(&foS[tv.y + 10 * ((s0 + 1) % NPH)], s0 + 1);
        __syncthreads();
        float A = asf_f();
        for (int task = tid; task < NCLS * NPH; task += 1024) {
            int q = task / NPH, p = task % NPH;
            int m = q % NPH - p; if (m < 0) m += NPH;
            float base = A * sdf[q / NPH] * cmf[m];
            int l1 = 1 << 28, l2 = 1 << 28;
            #pragma unroll
            for (int d = 0; d < NV; d++) {
                float L = base * sdf[d];
                int f = foS[d + 10 * p];
                if (L >= -6.0f)  l1 = min(l1, f);
                if (L >=  94.0f) l2 = min(l2, f);
            }
            atomicMin(&tt1[q], l1);
            atomicMin(&tt2[q], l2);
        }
        __syncthreads();
        if (tid < NCLS) {
            g_t1[bid * NCLS + tid] = tt1[tid];
            g_t2[bid * NCLS + tid] = tt2[tid];
        }
    } else if (bid < NB + 32) {
        // ---- histograms + exclusive 32-gran prefixes for half a batch ----
        int bx = bid - NB, hb = bx >> 1, half = bx & 1;
        int* hist = scratch;                 // [32][NCLSP]
        for (int i = tid; i < 32 * NCLSP; i += 1024) hist[i] = 0;
        __syncthreads();
        int s   = half * 1024 + tid;
        int cls = tokens[hb * LSEQ + s] + 10 * (s % NPH);
        atomicAdd(&hist[(tid >> 5) * NCLSP + cls], 1);
        __syncthreads();
        if (tid < NCLSP) {
            int run  = 0;
            int base = (hb * 64 + half * 32) * NCLSP + tid;
            #pragma unroll 4
            for (int sub = 0; sub < 32; sub++) {
                g_P[base + sub * NCLSP] = run;
                run += hist[sub * NCLSP + tid];
            }
            if (half == 0) g_T0[hb * NCLSP + tid] = run;
        }
    } else if (bid < NB + 32 + 107) {
        // ---- exp table: 1024 entries per block ----
        int idx = (bid - NB - 32) * 1024 + tid;
        if (idx < TAB_TOTAL) {
            int cls    = idx % NCLSP;
            int rest   = idx / NCLSP;
            int bucket = rest % NBUCK;
            int q      = rest / NBUCK;
            float2 r = make_float2(0.f, 0.f);
            if (cls < NCLS) {
                int dt = q / NPH, tp = q % NPH;
                int d  = cls % 10, p = cls / 10;
                int m  = tp - p; if (m < 0) m += NPH;
                float vd  = v[0];
                float L   = asf_f() * s_of(dt, c, ee) * s_of(d, c, ee) * cosm_f(m);
                float off = -56.0f + 100.0f * (float)bucket;
                float x   = expf(fminf(L - off, 60.0f)); // clamp hits only count-0 entries
                r = make_float2(x, x * vv0_of(d, c, ee, vd));
            }
            g_tab[idx] = r;
        }
    }

    // ================= grid barrier (ticket-window, no reset) =================
    // All 256 blocks are co-resident (2 blocks/SM x 148 SMs = 296 slots), so
    // spinning is deadlock-free. Launches serialize, so each launch's tickets
    // form a 256-aligned window: target = window_base + 256.
    __syncthreads();
    __threadfence();
    if (tid == 0) {
        unsigned t = atomicAdd(&g_bar, 1u);
        unsigned target = (t & ~255u) + 256u;
        while (*(volatile unsigned*)&g_bar < target) __nanosleep(64);
        __threadfence();
    }
    __syncthreads();

    // ================= phase B: cumulative-histogram softmax =================
    // prefix bases: at most 2 L2-hot LDGs per scan thread
    if (tid < 768) {
        int grp = tid / NCLSP, cl = tid % NCLSP;
        int sg  = ch * 4 + grp;                  // global 32-subchunk index
        int basec = g_P[(b * 64 + sg) * NCLSP + cl];
        if (ch >= 8) basec += g_T0[b * NCLSP + cl];
        // inclusive cumulative counts, four 32-row quarters in parallel
        int p0 = grp * 32, cnt = basec;
        #pragma unroll 8
        for (int p = p0; p < p0 + 32; p++) {
            cnt += (cls_sh[p] == cl);
            cnt_sh[p * NCLSP + cl] = (uint16_t)cnt;
        }
    } else if (tid < 896) {
        int i = tid - 768;                       // 128 threads: thresholds
        for (int q = i; q < NCLS; q += 128) {
            t1S[q] = g_t1[b * NCLS + q];
            t2S[q] = g_t2[b * NCLS + q];
        }
    }
    __syncthreads();

    float osc = o_scale[0];
    float ga  = g_base[0], gc = g_slope[0], ca = carry_amp[0];

    int w    = tid >> 5, lane = tid & 31;
    int half = lane >> 4, ll = lane & 15;        // 2 rows per warp, 16 lanes each
    const uint32_t* cnt32 = (const uint32_t*)cnt_sh;

    #pragma unroll
    for (int it = 0; it < 2; it++) {
        int r  = w * 4 + it * 2 + half;
        int t  = T0 + r;
        int dt = tok_sh[r];
        int q  = dt * NPH + (t % NPH);
        int bucket = (t >= t1S[q]) + (t >= t2S[q]);

        const float4* Tb = (const float4*)(g_tab + (q * NBUCK + bucket) * NCLSP);
        int cbase = r * (NCLSP / 2);

        float den = 0.f, num = 0.f;
        #pragma unroll
        for (int j = 0; j < 3; j++) {
            // lane ll covers classes j*64 + ll*4 .. +3 (coalesced 512B per half)
            float4 ea = __ldg(Tb + j * 32 + ll * 2);
            float4 eb = __ldg(Tb + j * 32 + ll * 2 + 1);
            uint2  u  = *(const uint2*)(cnt32 + cbase + j * 32 + ll * 2);
            float c0 = (float)(u.x & 0xffff), c1 = (float)(u.x >> 16);
            float c2 = (float)(u.y & 0xffff), c3 = (float)(u.y >> 16);
            den += c0 * ea.x + c1 * ea.z + c2 * eb.x + c3 * eb.z;
            num += c0 * ea.y + c1 * ea.w + c2 * eb.y + c3 * eb.w;
        }
        #pragma unroll
        for (int o = 8; o; o >>= 1) {            // 4-level butterfly within half
            den += __shfl_xor_sync(0xffffffffu, den, o);
            num += __shfl_xor_sync(0xffffffffu, num, o);
        }
        float attn = __fdividef(num, den);

        // fused epilogue (mirrors reference fp32 math)
        float h0 = c - ee * (float)(dt * dt);
        float h1 = -(float)dt + osc * attn;
        float rn = rsqrtf((h0 * h0 + h1 * h1) * 0.5f + 1e-6f);
        float hn0 = h0 * rn, hn1 = h1 * rn;
        float g0  = hn0 * ga + hn1 * gc;
        float g1  = hn0 * (ga - gc / c) + hn1 * gc;
        float carry = ca * (fmaxf(g1, 0.f) * hn0 - fmaxf(g0, 0.f) * hn0);
        float h1c = h1 + carry;
        float r2  = rsqrtf((h0 * h0 + h1c * h1c) * 0.5f + 1e-6f);
        const float inv_cn = 0.7071067811865475f;      // 1/sqrt(MODEL_DIM)
        float a0o = h0  * r2 * (0.1f * c * inv_cn);
        float a1o = h1c * r2 * (-c * 0.02f * inv_cn);  // -c/(50*sqrt2)
        if (ll < NV) {                                  // both halves store (20 lanes)
            float t0  = c - ee * (float)(ll * ll);
            float t1v = -(float)ll;
            out[(b * LSEQ + t) * NV + ll] = a0o * t0 + a1o * t1v;
        }
    }
}

// ---------------- launch ----------------
extern "C" void kernel_launch(void* const* d_in, const int* in_sizes, int n_in,
                              void* d_out, int out_size) {
    const int*   tokens    = (const int*)  d_in[0];
    const float* C         = (const float*)d_in[1];
    const float* eps       = (const float*)d_in[2];
    const float* v         = (const float*)d_in[3];
    const float* o_scale   = (const float*)d_in[4];
    const float* g_base    = (const float*)d_in[5];
    const float* g_slope   = (const float*)d_in[6];
    const float* carry_amp = (const float*)d_in[7];
    float* out = (float*)d_out;

    const int smem = CH128 * NCLSP * (int)sizeof(uint16_t);   // 49152
    cudaFuncSetAttribute(k_fused, cudaFuncAttributeMaxDynamicSharedMemorySize, smem);

    k_fused<<<GRID, 1024, smem>>>(tokens, C, eps, v, o_scale, g_base, g_slope,
                                  carry_amp, out);
}

// round 16
// speedup vs baseline: 1.3130x; 1.0152x over previous
#include <cuda_runtime.h>
#include <math.h>
#include <stdint.h>

#define NB      16
#define LSEQ    2048
#define NV      10
#define NPH     19
#define NCLS    190
#define NCLSP   192
#define NBUCK   3
#define CH128   128
#define TAB_TOTAL (NCLS * NBUCK * NCLSP)          // 109440
#define GRID    (NB * 16)                         // 256 blocks
#define NT      512

// ---------------- device scratch (static, allocation-free) ----------------
__device__ int g_P [NB * 64 * NCLSP];             // exclusive 32-gran prefix (within half)
__device__ int g_T0[NB * NCLSP];                  // per-class total of half 0
__device__ int g_t1[NB * NCLS];
__device__ int g_t2[NB * NCLS];
__device__ __align__(16) float2 g_tab[TAB_TOTAL]; // {e, e*vv0} per (q,bucket,cls)
__device__ unsigned g_bar = 0;                    // monotonic grid-barrier ticket

// ---------------- fp32 constants (no fp64 anywhere) ----------------
__device__ __forceinline__ float omega_f() { return 6.28318530717958647692f / 19.0f; }
// cancellation-free: cos(.3w)-cos(.7w) = 2 sin(.5w) sin(.2w); ATTN_SCALE = amp/2
__device__ __forceinline__ float asf_f() {
    float om = omega_f();
    return 2.302585092994046f / (4.0f * sinf(0.5f * om) * sinf(0.2f * om));
}
__device__ __forceinline__ float cosm_f(int m) {   // cos(om*m - phi), phi = om*10.3
    return cosf(omega_f() * ((float)m - 10.3f));
}
__device__ __forceinline__ float s_of(int d, float c, float e) {
    float h0 = c - e * (float)(d * d);
    float h1 = -(float)d;
    float r  = rsqrtf((h0 * h0 + h1 * h1) * 0.5f + 1e-6f);
    float hn0 = h0 * r;
    return hn0 * rsqrtf(hn0 * hn0 * 0.5f + 1e-6f);
}
__device__ __forceinline__ float vv0_of(int d, float c, float e, float v) {
    float h0 = c - e * (float)(d * d);
    float h1 = -(float)d;
    float r  = rsqrtf((h0 * h0 + h1 * h1) * 0.5f + 1e-6f);
    return h1 * r * v;
}

// ---------------- fused kernel: prep (phase A) + grid barrier + softmax (B) ----
__global__ void __launch_bounds__(NT, 2) k_fused(
    const int*   __restrict__ tokens,
    const float* __restrict__ C,        const float* __restrict__ eps,
    const float* __restrict__ v,
    const float* __restrict__ o_scale,  const float* __restrict__ g_base,
    const float* __restrict__ g_slope,  const float* __restrict__ carry_amp,
    float* __restrict__ out)
{
    extern __shared__ uint16_t cnt_sh[];   // phase B: [CH128][NCLSP] cumulative counts
    int* scratch = (int*)cnt_sh;           // phase A scratch (12288 ints)
    __shared__ int   tok_sh[CH128];
    __shared__ int   cls_sh[CH128];
    __shared__ int   t1S[NCLS], t2S[NCLS];
    __shared__ float sdf[NV], cmf[NPH];

    int bid = blockIdx.x, tid = threadIdx.x;
    int b   = bid >> 4;
    int ch  = bid & 15;
    int T0  = ch * CH128;

    float c  = C[0], ee = eps[0];

    // tokens/classes for phase B (independent of prep, overlaps phase A)
    if (tid < CH128) {
        int tk = tokens[b * LSEQ + T0 + tid];
        tok_sh[tid] = tk;
        cls_sh[tid] = tk + 10 * ((T0 + tid) % NPH);
    }

    // ================= phase A: distributed prep =================
    if (bid < NB) {
        // ---- bucket thresholds for batch `bid` ----
        int* foS = scratch;
        int* tt1 = scratch + 256;
        int* tt2 = scratch + 512;
        if (tid < NCLSP) foS[tid] = 1 << 20;
        if (tid < NV)    sdf[tid] = s_of(tid, c, ee);
        if (tid < NPH)   cmf[tid] = cosm_f(tid);
        if (tid < NCLS)  { tt1[tid] = 1 << 28; tt2[tid] = 1 << 28; }
        __syncthreads();
        int4 tv = ((const int4*)(tokens + bid * LSEQ))[tid];
        int s0 = tid * 4;
        atomicMin(&foS[tv.x + 10 * ( s0      % NPH)], s0);
        atomicMin(&foS[tv.y + 10 * ((s0 + 1) % NPH)], s0 + 1);
        atomicMin(&foS[tv.z + 10 * ((s0 + 2) % NPH)], s0 + 2);
        atomicMin(&foS[tv.w + 10 * ((s0 + 3) % NPH)], s0 + 3);
        __syncthreads();
        float A = asf_f();
        for (int task = tid; task < NCLS * NPH; task += NT) {
            int q = task / NPH, p = task % NPH;
            int m = q % NPH - p; if (m < 0) m += NPH;
            float base = A * sdf[q / NPH] * cmf[m];
            int l1 = 1 << 28, l2 = 1 << 28;
            #pragma unroll
            for (int d = 0; d < NV; d++) {
                float L = base * sdf[d];
                int f = foS[d + 10 * p];
                if (L >= -6.0f)  l1 = min(l1, f);
                if (L >=  94.0f) l2 = min(l2, f);
            }
            atomicMin(&tt1[q], l1);
            atomicMin(&tt2[q], l2);
        }
        __syncthreads();
        if (tid < NCLS) {
            g_t1[bid * NCLS + tid] = tt1[tid];
            g_t2[bid * NCLS + tid] = tt2[tid];
        }
    } else if (bid < NB + 32) {
        // ---- histograms + exclusive 32-gran prefixes for half a batch ----
        int bx = bid - NB, hb = bx >> 1, half = bx & 1;
        int* hist = scratch;                 // [32][NCLSP]
        for (int i = tid; i < 32 * NCLSP; i += NT) hist[i] = 0;
        __syncthreads();
        int s0 = half * 1024 + tid;          // two positions per thread
        int c0 = tokens[hb * LSEQ + s0]       + 10 * ( s0        % NPH);
        int c1 = tokens[hb * LSEQ + s0 + NT]  + 10 * ((s0 + NT)  % NPH);
        atomicAdd(&hist[ (tid >> 5)       * NCLSP + c0], 1);
        atomicAdd(&hist[((tid >> 5) + 16) * NCLSP + c1], 1);
        __syncthreads();
        if (tid < NCLSP) {
            int run  = 0;
            int base = (hb * 64 + half * 32) * NCLSP + tid;
            #pragma unroll 4
            for (int sub = 0; sub < 32; sub++) {
                g_P[base + sub * NCLSP] = run;
                run += hist[sub * NCLSP + tid];
            }
            if (half == 0) g_T0[hb * NCLSP + tid] = run;
        }
    } else if (bid < NB + 32 + 107) {
        // ---- exp table: 1024 entries per block, 2 per thread ----
        int base_i = (bid - NB - 32) * 1024 + tid;
        #pragma unroll
        for (int rep = 0; rep < 2; rep++) {
            int idx = base_i + rep * NT;
            if (idx < TAB_TOTAL) {
                int cls    = idx % NCLSP;
                int rest   = idx / NCLSP;
                int bucket = rest % NBUCK;
                int q      = rest / NBUCK;
                float2 r = make_float2(0.f, 0.f);
                if (cls < NCLS) {
                    int dt = q / NPH, tp = q % NPH;
                    int d  = cls % 10, p = cls / 10;
                    int m  = tp - p; if (m < 0) m += NPH;
                    float vd  = v[0];
                    float L   = asf_f() * s_of(dt, c, ee) * s_of(d, c, ee) * cosm_f(m);
                    float off = -56.0f + 100.0f * (float)bucket;
                    float x   = expf(fminf(L - off, 60.0f)); // clamp: count-0 entries only
                    r = make_float2(x, x * vv0_of(d, c, ee, vd));
                }
                g_tab[idx] = r;
            }
        }
    }

    // ================= grid barrier (ticket-window, no reset) =================
    // 256 blocks co-resident (2 blocks/SM by regs x 148 SMs = 296 slots) -> safe.
    __syncthreads();
    __threadfence();
    if (tid == 0) {
        unsigned t = atomicAdd(&g_bar, 1u);
        unsigned target = (t & ~255u) + 256u;
        while (*(volatile unsigned*)&g_bar < target) __nanosleep(64);
        __threadfence();
    }
    __syncthreads();

    // ================= phase B: cumulative-histogram softmax =================
    // count scan: 384 threads, two 32-row quarter passes each
    if (tid < 384) {
        int grp2 = tid / NCLSP, cl = tid % NCLSP;
        #pragma unroll
        for (int pass = 0; pass < 2; pass++) {
            int g  = grp2 + pass * 2;            // quarter 0..3
            int sg = ch * 4 + g;
            int cnt = g_P[(b * 64 + sg) * NCLSP + cl];
            if (ch >= 8) cnt += g_T0[b * NCLSP + cl];
            int p0 = g * 32;
            #pragma unroll 8
            for (int p = p0; p < p0 + 32; p++) {
                cnt += (cls_sh[p] == cl);
                cnt_sh[p * NCLSP + cl] = (uint16_t)cnt;
            }
        }
    } else {
        int i = tid - 384;                       // 128 threads: thresholds
        for (int q = i; q < NCLS; q += 128) {
            t1S[q] = g_t1[b * NCLS + q];
            t2S[q] = g_t2[b * NCLS + q];
        }
    }
    __syncthreads();

    float osc = o_scale[0];
    float ga  = g_base[0], gc = g_slope[0], ca = carry_amp[0];

    int w    = tid >> 5, lane = tid & 31;        // 16 warps, 8 rows each
    int half = lane >> 4, ll = lane & 15;        // 2 rows per warp-iteration
    const uint32_t* cnt32 = (const uint32_t*)cnt_sh;

    // precompute per-iteration row pointers so loads can be hoisted/pipelined
    const float4* Tbp[4];
    int cbp[4], dts[4];
    #pragma unroll
    for (int it = 0; it < 4; it++) {
        int r  = w * 8 + it * 2 + half;
        int t  = T0 + r;
        int dt = tok_sh[r];
        int q  = dt * NPH + (t % NPH);
        int bucket = (t >= t1S[q]) + (t >= t2S[q]);
        Tbp[it] = (const float4*)(g_tab + (q * NBUCK + bucket) * NCLSP);
        cbp[it] = r * (NCLSP / 2);
        dts[it] = dt;
    }

    #pragma unroll
    for (int it = 0; it < 4; it++) {
        const float4* Tb = Tbp[it];
        int cbase = cbp[it];
        int dt    = dts[it];
        int t     = T0 + w * 8 + it * 2 + half;

        // independent loads (64-reg budget lets ptxas keep multiple in flight)
        float4 ea0 = __ldg(Tb + ll * 2);
        float4 eb0 = __ldg(Tb + ll * 2 + 1);
        float4 ea1 = __ldg(Tb + 32 + ll * 2);
        float4 eb1 = __ldg(Tb + 32 + ll * 2 + 1);
        float4 ea2 = __ldg(Tb + 64 + ll * 2);
        float4 eb2 = __ldg(Tb + 64 + ll * 2 + 1);
        uint2  u0  = *(const uint2*)(cnt32 + cbase      + ll * 2);
        uint2  u1  = *(const uint2*)(cnt32 + cbase + 32 + ll * 2);
        uint2  u2  = *(const uint2*)(cnt32 + cbase + 64 + ll * 2);

        float den, num;
        {
            float c0 = (float)(u0.x & 0xffff), c1 = (float)(u0.x >> 16);
            float c2 = (float)(u0.y & 0xffff), c3 = (float)(u0.y >> 16);
            den  = c0 * ea0.x + c1 * ea0.z + c2 * eb0.x + c3 * eb0.z;
            num  = c0 * ea0.y + c1 * ea0.w + c2 * eb0.y + c3 * eb0.w;
            c0 = (float)(u1.x & 0xffff); c1 = (float)(u1.x >> 16);
            c2 = (float)(u1.y & 0xffff); c3 = (float)(u1.y >> 16);
            den += c0 * ea1.x + c1 * ea1.z + c2 * eb1.x + c3 * eb1.z;
            num += c0 * ea1.y + c1 * ea1.w + c2 * eb1.y + c3 * eb1.w;
            c0 = (float)(u2.x & 0xffff); c1 = (float)(u2.x >> 16);
            c2 = (float)(u2.y & 0xffff); c3 = (float)(u2.y >> 16);
            den += c0 * ea2.x + c1 * ea2.z + c2 * eb2.x + c3 * eb2.z;
            num += c0 * ea2.y + c1 * ea2.w + c2 * eb2.y + c3 * eb2.w;
        }
        #pragma unroll
        for (int o = 8; o; o >>= 1) {            // 4-level butterfly within half
            den += __shfl_xor_sync(0xffffffffu, den, o);
            num += __shfl_xor_sync(0xffffffffu, num, o);
        }
        float attn = __fdividef(num, den);

        // fused epilogue (mirrors reference fp32 math)
        float h0 = c - ee * (float)(dt * dt);
        float h1 = -(float)dt + osc * attn;
        float rn = rsqrtf((h0 * h0 + h1 * h1) * 0.5f + 1e-6f);
        float hn0 = h0 * rn, hn1 = h1 * rn;
        float g0  = hn0 * ga + hn1 * gc;
        float g1  = hn0 * (ga - gc / c) + hn1 * gc;
        float carry = ca * (fmaxf(g1, 0.f) * hn0 - fmaxf(g0, 0.f) * hn0);
        float h1c = h1 + carry;
        float r2  = rsqrtf((h0 * h0 + h1c * h1c) * 0.5f + 1e-6f);
        const float inv_cn = 0.7071067811865475f;      // 1/sqrt(MODEL_DIM)
        float a0o = h0  * r2 * (0.1f * c * inv_cn);
        float a1o = h1c * r2 * (-c * 0.02f * inv_cn);  // -c/(50*sqrt2)
        if (ll < NV) {                                  // both halves store
            float t0  = c - ee * (float)(ll * ll);
            float t1v = -(float)ll;
            out[(b * LSEQ + t) * NV + ll] = a0o * t0 + a1o * t1v;
        }
    }
}

// ---------------- launch ----------------
extern "C" void kernel_launch(void* const* d_in, const int* in_sizes, int n_in,
                              void* d_out, int out_size) {
    const int*   tokens    = (const int*)  d_in[0];
    const float* C         = (const float*)d_in[1];
    const float* eps       = (const float*)d_in[2];
    const float* v         = (const float*)d_in[3];
    const float* o_scale   = (const float*)d_in[4];
    const float* g_base    = (const float*)d_in[5];
    const float* g_slope   = (const float*)d_in[6];
    const float* carry_amp = (const float*)d_in[7];
    float* out = (float*)d_out;

    const int smem = CH128 * NCLSP * (int)sizeof(uint16_t);   // 49152
    cudaFuncSetAttribute(k_fused, cudaFuncAttributeMaxDynamicSharedMemorySize, smem);

    k_fused<<<GRID, NT, smem>>>(tokens, C, eps, v, o_scale, g_base, g_slope,
                                carry_amp, out);
}